// round 1
// baseline (speedup 1.0000x reference)
#include <cuda_runtime.h>
#include <cstdint>
#include <cstddef>

// CRF log-likelihood: sum_b (log_numerator - log_denominator)
// Denominator via SCALED forward algorithm (probability space):
//   p_t[j] = (sum_i p_{t-1}[i] * E[i][j]) * exp(emit_t[j]),  E = exp(transitions)
//   invariant: alpha_t[j] = C + log p_t[j];  rescale (C += log S, p /= S) every 8 steps.
// This turns 2500 exps/step into 2500 FMAs/step + 50 exps/step.

#define T_FIXED 512
#define KI 56          // padded inner (i) dimension, multiple of 8
#define PLEN 64        // padded p vector length (2 cols per lane * 32 lanes)
#define BMAX 1024

__device__ float g_EA[KI * 32];   // g_EA[i*32 + lane] = E[i][2*lane]
__device__ float g_EB[KI * 32];   // g_EB[i*32 + lane] = E[i][2*lane+1]
__device__ float g_es[PLEN];      // exp(start_transitions), zero-padded
__device__ float g_ee[PLEN];      // exp(end_transitions), zero-padded
__device__ float g_den[BMAX];
__device__ float g_res[BMAX];

__global__ void prep_kernel(const float* __restrict__ trans,
                            const float* __restrict__ st,
                            const float* __restrict__ en, int K) {
    int idx = blockIdx.x * blockDim.x + threadIdx.x;
    if (idx < KI * 32) {
        int i = idx >> 5, lane = idx & 31;
        int j0 = 2 * lane, j1 = 2 * lane + 1;
        g_EA[idx] = (i < K && j0 < K) ? expf(trans[i * K + j0]) : 0.f;
        g_EB[idx] = (i < K && j1 < K) ? expf(trans[i * K + j1]) : 0.f;
    }
    if (idx < PLEN) {
        g_es[idx] = (idx < K) ? expf(st[idx]) : 0.f;
        g_ee[idx] = (idx < K) ? expf(en[idx]) : 0.f;
    }
}

__global__ __launch_bounds__(128) void fwd_kernel(
    const float* __restrict__ logits, const int* __restrict__ mask,
    int B, int T, int K) {
    const int warp = threadIdx.x >> 5;
    const int lane = threadIdx.x & 31;
    const int b = blockIdx.x * 4 + warp;
    __shared__ __align__(16) float p_sh[4][PLEN];
    if (b >= B) return;
    float* p = p_sh[warp];

    // Each thread owns E columns (2*lane, 2*lane+1) in registers: reused T times.
    float EA[KI], EB[KI];
#pragma unroll
    for (int i = 0; i < KI; i++) {
        EA[i] = g_EA[i * 32 + lane];
        EB[i] = g_EB[i * 32 + lane];
    }

    const int o2 = 2 * lane;
    const bool valid = (o2 + 1) < K;   // K is even (50); both columns real iff this
    const float* lrow = logits + (size_t)b * T * K;
    const int* mrow = mask + (size_t)b * T;
    const float es0 = g_es[o2], es1 = g_es[o2 + 1];

    // t = 0: p = exp(start) * exp(emit0), C = 0 (unconditional, matches reference)
    float w0, w1;
    {
        float2 e = valid ? *(const float2*)(lrow + o2) : make_float2(0.f, 0.f);
        w0 = es0 * __expf(e.x);
        w1 = es1 * __expf(e.y);
    }
    *(float2*)(p + o2) = make_float2(w0, w1);
    float C = 0.f;
    __syncwarp();

    // software-pipelined emit load (one step ahead)
    float2 e = valid ? *(const float2*)(lrow + K + o2) : make_float2(0.f, 0.f);

    for (int t = 1; t < T; t++) {
        int m = mrow[t];                  // uniform across warp
        float x0 = __expf(e.x), x1 = __expf(e.y);
        if (t + 1 < T && valid)
            e = *(const float2*)(lrow + (size_t)(t + 1) * K + o2);

        // mat-vec: s[j] = sum_i p[i] * E[i][j]; 4 accumulator chains for ILP
        float s0a = 0.f, s0b = 0.f, s1a = 0.f, s1b = 0.f;
#pragma unroll
        for (int i = 0; i < KI; i += 8) {
            float4 pv = *(const float4*)(p + i);
            float4 pw = *(const float4*)(p + i + 4);
            s0a = fmaf(pv.x, EA[i + 0], s0a); s1a = fmaf(pv.x, EB[i + 0], s1a);
            s0a = fmaf(pv.y, EA[i + 1], s0a); s1a = fmaf(pv.y, EB[i + 1], s1a);
            s0a = fmaf(pv.z, EA[i + 2], s0a); s1a = fmaf(pv.z, EB[i + 2], s1a);
            s0a = fmaf(pv.w, EA[i + 3], s0a); s1a = fmaf(pv.w, EB[i + 3], s1a);
            s0b = fmaf(pw.x, EA[i + 4], s0b); s1b = fmaf(pw.x, EB[i + 4], s1b);
            s0b = fmaf(pw.y, EA[i + 5], s0b); s1b = fmaf(pw.y, EB[i + 5], s1b);
            s0b = fmaf(pw.z, EA[i + 6], s0b); s1b = fmaf(pw.z, EB[i + 6], s1b);
            s0b = fmaf(pw.w, EA[i + 7], s0b); s1b = fmaf(pw.w, EB[i + 7], s1b);
        }
        if (m) {   // mask==0 freezes alpha: skip update
            w0 = (s0a + s0b) * x0;
            w1 = (s1a + s1b) * x1;
            *(float2*)(p + o2) = make_float2(w0, w1);
        }
        __syncwarp();

        // periodic rescale: keeps p in fp32 range, amortizes log/reduce over 8 steps
        if ((t & 7) == 7) {
            float s = w0 + w1;
#pragma unroll
            for (int off = 16; off > 0; off >>= 1)
                s += __shfl_xor_sync(0xffffffffu, s, off);
            C += __logf(s);
            float inv = __frcp_rn(s);
            w0 *= inv; w1 *= inv;
            *(float2*)(p + o2) = make_float2(w0, w1);
            __syncwarp();
        }
    }

    // log Z = C + log( sum_j p[j] * exp(end[j]) )
    float s = w0 * g_ee[o2] + w1 * g_ee[o2 + 1];
#pragma unroll
    for (int off = 16; off > 0; off >>= 1)
        s += __shfl_xor_sync(0xffffffffu, s, off);
    if (lane == 0) g_den[b] = C + __logf(s);
}

__global__ __launch_bounds__(128) void num_kernel(
    const float* __restrict__ logits, const float* __restrict__ trans,
    const float* __restrict__ st, const float* __restrict__ en,
    const int* __restrict__ tags, const int* __restrict__ mask,
    int B, int T, int K) {
    __shared__ float tr[2500];
    for (int i = threadIdx.x; i < K * K; i += blockDim.x) tr[i] = trans[i];
    __syncthreads();
    int warp = threadIdx.x >> 5, lane = threadIdx.x & 31;
    int b = blockIdx.x * 4 + warp;
    if (b >= B) return;
    const int* trow = tags + (size_t)b * T;
    const int* mrow = mask + (size_t)b * T;
    const float* lrow = logits + (size_t)b * T * K;
    float acc = 0.f;
    int msum = 0;
    for (int t = lane; t < T; t += 32) {
        int tg = trow[t];
        int mi = mrow[t];
        float m = (float)mi;
        msum += mi;
        if (t >= 1)    acc += tr[trow[t - 1] * K + tg] * m;     // transition score, t=1..T-1
        if (t < T - 1) acc += lrow[(size_t)t * K + tg] * m;     // emit score, t=0..T-2
    }
#pragma unroll
    for (int off = 16; off > 0; off >>= 1) {
        acc  += __shfl_xor_sync(0xffffffffu, acc, off);
        msum += __shfl_xor_sync(0xffffffffu, msum, off);
    }
    if (lane == 0) {
        int last = msum - 1;
        if (last < 0) last += T;          // mimic jnp wrap-around on index -1
        int lt = trow[last];
        float sc = acc + st[trow[0]] + en[lt]
                 + lrow[(size_t)(T - 1) * K + lt] * (float)mrow[T - 1];
        g_res[b] = sc - g_den[b];
    }
}

__global__ void reduce_kernel(float* __restrict__ out, int B) {
    __shared__ double sd[256];
    int tid = threadIdx.x;
    double s = 0.0;
    for (int i = tid; i < B; i += 256) s += (double)g_res[i];
    sd[tid] = s;
    __syncthreads();
    for (int k = 128; k > 0; k >>= 1) {
        if (tid < k) sd[tid] += sd[tid + k];
        __syncthreads();
    }
    if (tid == 0) out[0] = (float)sd[0];
}

extern "C" void kernel_launch(void* const* d_in, const int* in_sizes, int n_in,
                              void* d_out, int out_size) {
    const float* logits = (const float*)d_in[0];
    const float* trans  = (const float*)d_in[1];
    const float* st     = (const float*)d_in[2];
    const float* en     = (const float*)d_in[3];
    const int*   tags   = (const int*)d_in[4];
    const int*   mask   = (const int*)d_in[5];

    int K  = in_sizes[2];       // 50
    int BT = in_sizes[4];       // B*T
    int T  = T_FIXED;           // 512 (fixed problem shape)
    int B  = BT / T;            // 1024

    prep_kernel<<<4, 512>>>(trans, st, en, K);
    int nb = (B + 3) / 4;
    fwd_kernel<<<nb, 128>>>(logits, mask, B, T, K);
    num_kernel<<<nb, 128>>>(logits, trans, st, en, tags, mask, B, T, K);
    reduce_kernel<<<1, 256>>>((float*)d_out, B);
}

// round 3
// speedup vs baseline: 1.1445x; 1.1445x over previous
#include <cuda_runtime.h>
#include <cstdint>
#include <cstddef>

// CRF log-likelihood: sum_b (log_numerator - log_denominator)
// Scaled forward algorithm in probability space with packed f32x2 FMAs:
//   p_t[j] = (sum_i p_{t-1}[i] * E[i][j]) * exp(emit_t[j]),  E = exp(transitions)
//   alpha_t = C + log p_t ; rescale every 8 steps.
// Each lane owns 2 output columns packed in one f32x2 lane-pair; p is stored
// DUPLICATED in shared ((p_i,p_i) pairs) so one LDS.128 yields two packed
// broadcast operands with no pack instructions in the hot loop.

#define T_FIXED 512
#define KMAX 50
#define NPAIR 25        // KMAX/2 float4 loads per step
#define PLEN 64
#define BMAX 1024
#define NW 8            // warps per block

typedef unsigned long long u64;

__device__ __forceinline__ u64 ffma2(u64 a, u64 b, u64 c) {
    u64 d; asm("fma.rn.f32x2 %0, %1, %2, %3;" : "=l"(d) : "l"(a), "l"(b), "l"(c));
    return d;
}
__device__ __forceinline__ u64 add2(u64 a, u64 b) {
    u64 d; asm("add.rn.f32x2 %0, %1, %2;" : "=l"(d) : "l"(a), "l"(b));
    return d;
}
__device__ __forceinline__ u64 mul2(u64 a, u64 b) {
    u64 d; asm("mul.rn.f32x2 %0, %1, %2;" : "=l"(d) : "l"(a), "l"(b));
    return d;
}
__device__ __forceinline__ u64 pack2(float lo, float hi) {
    u64 d; asm("mov.b64 %0, {%1, %2};" : "=l"(d) : "f"(lo), "f"(hi));
    return d;
}
__device__ __forceinline__ void unpack2(u64 v, float& lo, float& hi) {
    asm("mov.b64 {%0, %1}, %2;" : "=f"(lo), "=f"(hi) : "l"(v));
}

__device__ u64   g_E2[KMAX * 32];  // g_E2[i*32+lane] = (E[i][2*lane], E[i][2*lane+1]), 0-padded
__device__ float g_es[PLEN];       // exp(start_transitions), zero-padded
__device__ float g_ee[PLEN];       // exp(end_transitions), zero-padded
__device__ float g_den[BMAX];
__device__ float g_res[BMAX];

__global__ void prep_kernel(const float* __restrict__ trans,
                            const float* __restrict__ st,
                            const float* __restrict__ en, int K) {
    int idx = blockIdx.x * blockDim.x + threadIdx.x;
    if (idx < KMAX * 32) {
        int i = idx >> 5, lane = idx & 31;
        int j0 = 2 * lane, j1 = 2 * lane + 1;
        float a = (i < K && j0 < K) ? expf(trans[i * K + j0]) : 0.f;
        float b = (i < K && j1 < K) ? expf(trans[i * K + j1]) : 0.f;
        g_E2[idx] = pack2(a, b);
    }
    if (idx < PLEN) {
        g_es[idx] = (idx < K) ? expf(st[idx]) : 0.f;
        g_ee[idx] = (idx < K) ? expf(en[idx]) : 0.f;
    }
}

__global__ __launch_bounds__(256) void fwd_kernel(
    const float* __restrict__ logits, const int* __restrict__ mask,
    int B, int T, int K) {
    const int warp = threadIdx.x >> 5;
    const int lane = threadIdx.x & 31;
    const int b = blockIdx.x * NW + warp;
    // double-buffered duplicated-p: pd[warp][buf][i] holds ((p_2i,p_2i),(p_2i+1,p_2i+1))
    __shared__ __align__(16) ulonglong2 pd[NW][2][32];
    if (b >= B) return;

    // E columns (2*lane, 2*lane+1) packed in registers, reused T times
    u64 Ep[KMAX];
#pragma unroll
    for (int i = 0; i < KMAX; i++) Ep[i] = g_E2[i * 32 + lane];

    const int o2 = 2 * lane;
    const int o2e = (o2 + 1 < K) ? o2 : 0;       // OOB-safe clamp for pad lanes
    const float* lrow = logits + (size_t)b * T * K;
    const int* mrow = mask + (size_t)b * T;
    const float ee0 = g_ee[o2], ee1 = g_ee[o2 + 1];

    // t = 0: p = exp(start)*exp(emit0). Pad lanes: es==0 -> w==0 everywhere.
    float w0, w1;
    {
        float2 e0 = *(const float2*)(lrow + o2e);
        w0 = g_es[o2] * __expf(e0.x);
        w1 = g_es[o2 + 1] * __expf(e0.y);
    }
    pd[warp][0][lane] = make_ulonglong2(pack2(w0, w0), pack2(w1, w1));
    float C = 0.f;
    __syncwarp();

    float2 e = *(const float2*)(lrow + K + o2e);   // prefetch emit for t=1

    for (int t = 1; t < T; t++) {
        int m = mrow[t];                                    // uniform
        float x0 = __expf(e.x), x1 = __expf(e.y);
        if (t + 1 < T)
            e = *(const float2*)(lrow + (size_t)(t + 1) * K + o2e);

        const ulonglong2* rb = pd[warp][(t - 1) & 1];
        u64 a0 = 0, a1 = 0, a2 = 0, a3 = 0;                 // 4 packed chains
#pragma unroll
        for (int i = 0; i < NPAIR; i += 2) {
            ulonglong2 q0 = rb[i];
            a0 = ffma2(q0.x, Ep[2 * i], a0);
            a1 = ffma2(q0.y, Ep[2 * i + 1], a1);
            if (i + 1 < NPAIR) {
                ulonglong2 q1 = rb[i + 1];
                a2 = ffma2(q1.x, Ep[2 * i + 2], a2);
                a3 = ffma2(q1.y, Ep[2 * i + 3], a3);
            }
        }
        u64 s = add2(add2(a0, a2), add2(a1, a3));
        u64 w = mul2(s, pack2(x0, x1));
        if (m) unpack2(w, w0, w1);                          // mask==0 freezes alpha
        pd[warp][t & 1][lane] = make_ulonglong2(pack2(w0, w0), pack2(w1, w1));
        __syncwarp();

        if ((t & 7) == 7) {                                 // periodic rescale
            float sr = w0 + w1;
#pragma unroll
            for (int off = 16; off > 0; off >>= 1)
                sr += __shfl_xor_sync(0xffffffffu, sr, off);
            C += __logf(sr);
            float inv = __frcp_rn(sr);
            w0 *= inv; w1 *= inv;
            pd[warp][t & 1][lane] = make_ulonglong2(pack2(w0, w0), pack2(w1, w1));
            __syncwarp();
        }
    }

    // log Z = C + log( sum_j p[j] * exp(end[j]) )
    float sr = w0 * ee0 + w1 * ee1;
#pragma unroll
    for (int off = 16; off > 0; off >>= 1)
        sr += __shfl_xor_sync(0xffffffffu, sr, off);
    if (lane == 0) g_den[b] = C + __logf(sr);
}

__global__ __launch_bounds__(256) void num_kernel(
    const float* __restrict__ logits, const float* __restrict__ trans,
    const float* __restrict__ st, const float* __restrict__ en,
    const int* __restrict__ tags, const int* __restrict__ mask,
    int B, int T, int K) {
    __shared__ float tr[2500];
    for (int i = threadIdx.x; i < K * K; i += blockDim.x) tr[i] = trans[i];
    __syncthreads();
    int warp = threadIdx.x >> 5, lane = threadIdx.x & 31;
    int b = blockIdx.x * NW + warp;
    if (b >= B) return;
    const int* trow = tags + (size_t)b * T;
    const int* mrow = mask + (size_t)b * T;
    const float* lrow = logits + (size_t)b * T * K;
    float acc = 0.f;
    int msum = 0;
    for (int t = lane; t < T; t += 32) {
        int tg = trow[t];
        int mi = mrow[t];
        float m = (float)mi;
        msum += mi;
        if (t >= 1)    acc += tr[trow[t - 1] * K + tg] * m;   // transitions t=1..T-1
        if (t < T - 1) acc += lrow[(size_t)t * K + tg] * m;   // emits t=0..T-2
    }
#pragma unroll
    for (int off = 16; off > 0; off >>= 1) {
        acc  += __shfl_xor_sync(0xffffffffu, acc, off);
        msum += __shfl_xor_sync(0xffffffffu, msum, off);
    }
    if (lane == 0) {
        int last = msum - 1;
        if (last < 0) last += T;                // jnp wrap-around on index -1
        int lt = trow[last];
        float sc = acc + st[trow[0]] + en[lt]
                 + lrow[(size_t)(T - 1) * K + lt] * (float)mrow[T - 1];
        g_res[b] = sc - g_den[b];
    }
}

__global__ void reduce_kernel(float* __restrict__ out, int B) {
    __shared__ double sd[256];
    int tid = threadIdx.x;
    double s = 0.0;
    for (int i = tid; i < B; i += 256) s += (double)g_res[i];
    sd[tid] = s;
    __syncthreads();
    for (int k = 128; k > 0; k >>= 1) {
        if (tid < k) sd[tid] += sd[tid + k];
        __syncthreads();
    }
    if (tid == 0) out[0] = (float)sd[0];
}

extern "C" void kernel_launch(void* const* d_in, const int* in_sizes, int n_in,
                              void* d_out, int out_size) {
    const float* logits = (const float*)d_in[0];
    const float* trans  = (const float*)d_in[1];
    const float* st     = (const float*)d_in[2];
    const float* en     = (const float*)d_in[3];
    const int*   tags   = (const int*)d_in[4];
    const int*   mask   = (const int*)d_in[5];

    int K  = in_sizes[2];       // 50
    int BT = in_sizes[4];       // B*T
    int T  = T_FIXED;           // 512
    int B  = BT / T;            // 1024

    prep_kernel<<<4, 512>>>(trans, st, en, K);
    int nb = (B + NW - 1) / NW;                 // 128 blocks = 1/SM, one wave
    fwd_kernel<<<nb, 32 * NW>>>(logits, mask, B, T, K);
    num_kernel<<<nb, 32 * NW>>>(logits, trans, st, en, tags, mask, B, T, K);
    reduce_kernel<<<1, 256>>>((float*)d_out, B);
}

// round 5
// speedup vs baseline: 1.4285x; 1.2482x over previous
#include <cuda_runtime.h>
#include <cstdint>
#include <cstddef>

// CRF log-likelihood: sum_b (log_num - log_den), scaled forward algorithm.
//   p_t[j] = (sum_i p_{t-1}[i] * E[i][j]) * exp(emit_t[j]),  E = exp(transitions)
//   alpha_t = C + log p_t ; rescale every 8 steps.
// R3: depth-4 emit/mask prefetch rings (static register slots via 4x unroll),
//     paired-p layout (13 LDS.128/step instead of 25), numerator fused in.

#define T_FIXED 512
#define KMAX 50
#define NK2 26          // ceil(52/2): packed (i,i+1) pairs covering i=0..51
#define PLEN 64
#define BMAX 1024
#define NW 8

typedef unsigned long long u64;

__device__ __forceinline__ u64 ffma2(u64 a, u64 b, u64 c) {
    u64 d; asm("fma.rn.f32x2 %0, %1, %2, %3;" : "=l"(d) : "l"(a), "l"(b), "l"(c));
    return d;
}
__device__ __forceinline__ u64 add2(u64 a, u64 b) {
    u64 d; asm("add.rn.f32x2 %0, %1, %2;" : "=l"(d) : "l"(a), "l"(b));
    return d;
}
__device__ __forceinline__ u64 pack2(float lo, float hi) {
    u64 d; asm("mov.b64 %0, {%1, %2};" : "=l"(d) : "f"(lo), "f"(hi));
    return d;
}
__device__ __forceinline__ float2 unpack2f(u64 v) {
    float2 r; asm("mov.b64 {%0, %1}, %2;" : "=f"(r.x), "=f"(r.y) : "l"(v));
    return r;
}

// g_Epk[k*64 + j] = (E[2k][j], E[2k+1][j]) packed, zero-padded (k<26, j<64)
__device__ u64   g_Epk[NK2 * 64];
__device__ float g_es[PLEN];
__device__ float g_ee[PLEN];
__device__ float g_res[BMAX];

__global__ void prep_kernel(const float* __restrict__ trans,
                            const float* __restrict__ st,
                            const float* __restrict__ en, int K) {
    int idx = blockIdx.x * blockDim.x + threadIdx.x;
    if (idx < NK2 * 64) {
        int k = idx >> 6, j = idx & 63;
        int i0 = 2 * k, i1 = 2 * k + 1;
        float a = (i0 < K && j < K) ? expf(trans[i0 * K + j]) : 0.f;
        float b = (i1 < K && j < K) ? expf(trans[i1 * K + j]) : 0.f;
        g_Epk[idx] = pack2(a, b);
    }
    if (idx < PLEN) {
        g_es[idx] = (idx < K) ? expf(st[idx]) : 0.f;
        g_ee[idx] = (idx < K) ? expf(en[idx]) : 0.f;
    }
}

__global__ __launch_bounds__(256) void fwd_kernel(
    const float* __restrict__ logits, const float* __restrict__ trans,
    const float* __restrict__ st, const float* __restrict__ en,
    const int* __restrict__ tags, const int* __restrict__ mask,
    int B, int K) {
    const int T = T_FIXED;
    const int warp = threadIdx.x >> 5;
    const int lane = threadIdx.x & 31;
    const int b = blockIdx.x * NW + warp;
    __shared__ __align__(16) float p_sh[NW][2][PLEN];   // p stored ONCE (not duplicated)
    if (b >= B) return;
    float* const p0 = p_sh[warp][0];
    float* const p1 = p_sh[warp][1];

    // Per-thread E columns j0=2*lane, j1=2*lane+1 as packed (i,i+1) pairs.
    u64 EA[NK2], EB[NK2];
#pragma unroll
    for (int k = 0; k < NK2; k++) {
        EA[k] = g_Epk[k * 64 + 2 * lane];
        EB[k] = g_Epk[k * 64 + 2 * lane + 1];
    }

    const int o2 = 2 * lane;
    const int o2e = (o2 + 1 < K) ? o2 : 0;       // OOB-safe clamp for pad lanes
    const float* lrow = logits + (size_t)b * T * K;
    const int* mrow = mask + (size_t)b * T;

    // t = 0
    float w0, w1;
    {
        float2 e0 = *(const float2*)(lrow + o2e);
        w0 = g_es[o2] * __expf(e0.x);        // pad lanes: es==0 -> w==0 forever
        w1 = g_es[o2 + 1] * __expf(e0.y);
    }
    *(float2*)(p0 + o2) = make_float2(w0, w1);
    float C = 0.f;
    __syncwarp();

    // depth-4 prefetch rings in STATIC register slots
    float2 e0s = *(const float2*)(lrow + (size_t)1 * K + o2e);
    float2 e1s = *(const float2*)(lrow + (size_t)2 * K + o2e);
    float2 e2s = *(const float2*)(lrow + (size_t)3 * K + o2e);
    float2 e3s = *(const float2*)(lrow + (size_t)4 * K + o2e);
    int m0s = mrow[1], m1s = mrow[2], m2s = mrow[3], m3s = mrow[4];

#define STEP(tt, ESLOT, MSLOT, RB, WB)                                         \
    {                                                                          \
        const int t_ = (tt);                                                   \
        float2 e_ = ESLOT;                                                     \
        int m_ = MSLOT;                                                        \
        if (t_ + 4 < T) {                                                      \
            ESLOT = *(const float2*)(lrow + (size_t)(t_ + 4) * K + o2e);       \
            MSLOT = mrow[t_ + 4];                                              \
        }                                                                      \
        float x0_ = __expf(e_.x), x1_ = __expf(e_.y);                          \
        const ulonglong2* rb_ = (const ulonglong2*)(RB);                       \
        u64 a0_ = 0, a1_ = 0, a2_ = 0, a3_ = 0;                                \
        _Pragma("unroll")                                                      \
        for (int q = 0; q < 13; q++) {                                         \
            ulonglong2 pv = rb_[q];                                            \
            a0_ = ffma2(pv.x, EA[2 * q], a0_);                                 \
            a2_ = ffma2(pv.x, EB[2 * q], a2_);                                 \
            a1_ = ffma2(pv.y, EA[2 * q + 1], a1_);                             \
            a3_ = ffma2(pv.y, EB[2 * q + 1], a3_);                             \
        }                                                                      \
        float2 sj0 = unpack2f(add2(a0_, a1_));                                 \
        float2 sj1 = unpack2f(add2(a2_, a3_));                                 \
        float nw0 = (sj0.x + sj0.y) * x0_;                                     \
        float nw1 = (sj1.x + sj1.y) * x1_;                                     \
        w0 = m_ ? nw0 : w0;                                                    \
        w1 = m_ ? nw1 : w1;                                                    \
        *(float2*)((WB) + o2) = make_float2(w0, w1);                           \
        __syncwarp();                                                          \
        if ((t_ & 7) == 7) {                                                   \
            float sr_ = w0 + w1;                                               \
            _Pragma("unroll")                                                  \
            for (int off = 16; off > 0; off >>= 1)                             \
                sr_ += __shfl_xor_sync(0xffffffffu, sr_, off);                 \
            C += __logf(sr_);                                                  \
            float inv_ = __frcp_rn(sr_);                                       \
            w0 *= inv_; w1 *= inv_;                                            \
            *(float2*)((WB) + o2) = make_float2(w0, w1);                       \
            __syncwarp();                                                      \
        }                                                                      \
    }

    int t = 1;
    for (; t + 3 < T; t += 4) {          // t odd at loop head: parity static
        STEP(t + 0, e0s, m0s, p0, p1)
        STEP(t + 1, e1s, m1s, p1, p0)
        STEP(t + 2, e2s, m2s, p0, p1)
        STEP(t + 3, e3s, m3s, p1, p0)
    }
    // T=512: t==509 here; 3 tail steps with static parity (509 odd)
    if (t + 2 < T) {                      // t, t+1, t+2 = 509,510,511
        STEP(t + 0, e0s, m0s, p0, p1)
        STEP(t + 1, e1s, m1s, p1, p0)
        STEP(t + 2, e2s, m2s, p0, p1)
    }
#undef STEP

    // log Z = C + log( sum_j p[j] * exp(end[j]) )  (uniform across lanes)
    float sr = w0 * g_ee[o2] + w1 * g_ee[o2 + 1];
#pragma unroll
    for (int off = 16; off > 0; off >>= 1)
        sr += __shfl_xor_sync(0xffffffffu, sr, off);
    const float den = C + __logf(sr);

    // ---- fused numerator ----
    const int* trow = tags + (size_t)b * T;
    float acc = 0.f;
    int msum = 0;
    for (int tt = lane; tt < T; tt += 32) {
        int tg = trow[tt];
        int mi = mrow[tt];
        float mf = (float)mi;
        msum += mi;
        if (tt >= 1)     acc += __ldg(trans + trow[tt - 1] * K + tg) * mf;
        if (tt < T - 1)  acc += lrow[(size_t)tt * K + tg] * mf;
    }
#pragma unroll
    for (int off = 16; off > 0; off >>= 1) {
        acc  += __shfl_xor_sync(0xffffffffu, acc, off);
        msum += __shfl_xor_sync(0xffffffffu, msum, off);
    }
    if (lane == 0) {
        int last = msum - 1;
        if (last < 0) last += T;            // jnp wrap-around on index -1
        int lt = trow[last];
        float sc = acc + st[trow[0]] + en[lt]
                 + lrow[(size_t)(T - 1) * K + lt] * (float)mrow[T - 1];
        g_res[b] = sc - den;
    }
}

__global__ void reduce_kernel(float* __restrict__ out, int B) {
    __shared__ double sd[256];
    int tid = threadIdx.x;
    double s = 0.0;
    for (int i = tid; i < B; i += 256) s += (double)g_res[i];
    sd[tid] = s;
    __syncthreads();
    for (int k = 128; k > 0; k >>= 1) {
        if (tid < k) sd[tid] += sd[tid + k];
        __syncthreads();
    }
    if (tid == 0) out[0] = (float)sd[0];
}

extern "C" void kernel_launch(void* const* d_in, const int* in_sizes, int n_in,
                              void* d_out, int out_size) {
    const float* logits = (const float*)d_in[0];
    const float* trans  = (const float*)d_in[1];
    const float* st     = (const float*)d_in[2];
    const float* en     = (const float*)d_in[3];
    const int*   tags   = (const int*)d_in[4];
    const int*   mask   = (const int*)d_in[5];

    int K  = in_sizes[2];        // 50
    int BT = in_sizes[4];        // B*T
    int B  = BT / T_FIXED;       // 1024

    prep_kernel<<<4, 512>>>(trans, st, en, K);
    int nb = (B + NW - 1) / NW;  // 128 blocks = 1/SM, one wave
    fwd_kernel<<<nb, 32 * NW>>>(logits, trans, st, en, tags, mask, B, K);
    reduce_kernel<<<1, 256>>>((float*)d_out, B);
}